// round 2
// baseline (speedup 1.0000x reference)
#include <cuda_runtime.h>
#include <cuda_bf16.h>

// Problem: o [N=16, C=32, D=32, H=64, W=64] fp32, bias [C] fp32.
// out[n] = (1/(2*16384)) * sum_{c, pooled cells} max_{2x2x2}(o) + sum_c bias_c
// Pure HBM-streaming reduction: 256 MB in, 64 B out.

#define N_  16
#define C_  32
#define D_  32
#define H_  64
#define W_  64
#define PD_ (D_/2)
// scale = 1/DIVISOR * 1/(PD*PH*PW) = 1/2 * 1/16384
#define SCALE_ (1.0f / 32768.0f)

// ---- init: out[n] = sum(bias) for all n (also clears the 0xAA poison) ----
__global__ void bias_init_kernel(const float* __restrict__ bias,
                                 float* __restrict__ out) {
    int lane = threadIdx.x;              // 32 threads, C_=32
    float b = bias[lane];
    #pragma unroll
    for (int off = 16; off > 0; off >>= 1)
        b += __shfl_xor_sync(0xFFFFFFFFu, b, off);
    if (lane < N_) out[lane] = b;
}

// ---- main: one block per (n, c, pd) slab; block reads 32 KB, does pooled sum ----
__global__ __launch_bounds__(256, 8)
void pool_reduce_kernel(const float* __restrict__ o,
                        float* __restrict__ out) {
    const int pd = blockIdx.x;   // 0..15
    const int c  = blockIdx.y;   // 0..31
    const int n  = blockIdx.z;   // 0..15
    const int tid = threadIdx.x; // 0..255

    // Base of this (n,c) volume + the 2 D-slices d = 2*pd, 2*pd+1.
    const size_t vol_base = (((size_t)n * C_ + c) * D_ + 2 * pd) * (H_ * W_);
    const float* base = o + vol_base;

    // Work items: PH(32) x (W/4=16) = 512 tiles; 256 threads -> 2 each.
    float acc = 0.0f;
    #pragma unroll
    for (int it = 0; it < 2; ++it) {
        const int item = tid + it * 256;
        const int ph = item >> 4;        // 0..31
        const int wg = item & 15;        // 0..15  (float4 group -> 4 w values)
        const int row0 = (2 * ph) * W_ + wg * 4;

        const float4 a0 = *reinterpret_cast<const float4*>(base + row0);
        const float4 a1 = *reinterpret_cast<const float4*>(base + row0 + W_);
        const float4 b0 = *reinterpret_cast<const float4*>(base + row0 + H_ * W_);
        const float4 b1 = *reinterpret_cast<const float4*>(base + row0 + H_ * W_ + W_);

        float mx = fmaxf(fmaxf(a0.x, a1.x), fmaxf(b0.x, b1.x));
        float my = fmaxf(fmaxf(a0.y, a1.y), fmaxf(b0.y, b1.y));
        float mz = fmaxf(fmaxf(a0.z, a1.z), fmaxf(b0.z, b1.z));
        float mw = fmaxf(fmaxf(a0.w, a1.w), fmaxf(b0.w, b1.w));

        acc += fmaxf(mx, my) + fmaxf(mz, mw);   // two pooled cells
    }

    // Block reduction: warp shuffle, then smem across 8 warps.
    #pragma unroll
    for (int off = 16; off > 0; off >>= 1)
        acc += __shfl_xor_sync(0xFFFFFFFFu, acc, off);

    __shared__ float warp_sums[8];
    const int warp = tid >> 5;
    const int lane = tid & 31;
    if (lane == 0) warp_sums[warp] = acc;
    __syncthreads();

    if (warp == 0) {
        float v = (lane < 8) ? warp_sums[lane] : 0.0f;
        #pragma unroll
        for (int off = 4; off > 0; off >>= 1)
            v += __shfl_xor_sync(0xFFFFFFFFu, v, off);
        if (lane == 0)
            atomicAdd(&out[n], v * SCALE_);
    }
}

extern "C" void kernel_launch(void* const* d_in, const int* in_sizes, int n_in,
                              void* d_out, int out_size) {
    const float* o    = (const float*)d_in[0];
    const float* bias = (const float*)d_in[1];
    float* out = (float*)d_out;

    bias_init_kernel<<<1, 32>>>(bias, out);

    dim3 grid(PD_, C_, N_);   // 16 x 32 x 16 = 8192 blocks
    pool_reduce_kernel<<<grid, 256>>>(o, out);
}

// round 7
// speedup vs baseline: 1.0118x; 1.0118x over previous
#include <cuda_runtime.h>
#include <cuda_bf16.h>

// Problem: o [N=16, C=32, D=32, H=64, W=64] fp32, bias [C] fp32.
// out[n] = (1/(2*16384)) * sum_{c, pooled cells} max_{2x2x2}(o) + sum_c bias_c
// Pure HBM-streaming reduction: 256 MB in, 64 B out.
// Single-kernel version: "last block per n" finishes the reduction, adds the
// bias sum, writes out[n], and resets the persistent scratch (graph-replay safe).

#define N_  16
#define C_  32
#define D_  32
#define H_  64
#define W_  64
#define PD_ (D_/2)
#define BLOCKS_PER_N (PD_ * C_)          // 512
// scale = 1/DIVISOR * 1/(PD*PH*PW) = 1/2 * 1/16384
#define SCALE_ (1.0f / 32768.0f)

// Persistent scratch (zero-initialized at module load; reset by last block
// every call, so every launch sees zeros).
__device__ float        g_scratch[N_];
__device__ unsigned int g_count[N_];

__global__ __launch_bounds__(256, 8)
void fused_pool_reduce_kernel(const float* __restrict__ o,
                              const float* __restrict__ bias,
                              float* __restrict__ out) {
    const int pd = blockIdx.x;   // 0..15
    const int c  = blockIdx.y;   // 0..31
    const int n  = blockIdx.z;   // 0..15
    const int tid = threadIdx.x; // 0..255

    // Base of this (n,c) volume + the 2 D-slices d = 2*pd, 2*pd+1.
    const size_t vol_base = (((size_t)n * C_ + c) * D_ + 2 * pd) * (H_ * W_);
    const float* base = o + vol_base;

    // Work items: PH(32) x (W/4=16) = 512 tiles; 256 threads -> 2 each.
    // Front-batch all 8 float4 loads (max MLP) before any math.
    const int item0 = tid;
    const int item1 = tid + 256;
    const int r0 = ((item0 >> 4) * 2) * W_ + (item0 & 15) * 4;
    const int r1 = ((item1 >> 4) * 2) * W_ + (item1 & 15) * 4;

    const float4 a00 = *reinterpret_cast<const float4*>(base + r0);
    const float4 a01 = *reinterpret_cast<const float4*>(base + r0 + W_);
    const float4 a02 = *reinterpret_cast<const float4*>(base + r0 + H_ * W_);
    const float4 a03 = *reinterpret_cast<const float4*>(base + r0 + H_ * W_ + W_);
    const float4 a10 = *reinterpret_cast<const float4*>(base + r1);
    const float4 a11 = *reinterpret_cast<const float4*>(base + r1 + W_);
    const float4 a12 = *reinterpret_cast<const float4*>(base + r1 + H_ * W_);
    const float4 a13 = *reinterpret_cast<const float4*>(base + r1 + H_ * W_ + W_);

    float m0x = fmaxf(fmaxf(a00.x, a01.x), fmaxf(a02.x, a03.x));
    float m0y = fmaxf(fmaxf(a00.y, a01.y), fmaxf(a02.y, a03.y));
    float m0z = fmaxf(fmaxf(a00.z, a01.z), fmaxf(a02.z, a03.z));
    float m0w = fmaxf(fmaxf(a00.w, a01.w), fmaxf(a02.w, a03.w));
    float m1x = fmaxf(fmaxf(a10.x, a11.x), fmaxf(a12.x, a13.x));
    float m1y = fmaxf(fmaxf(a10.y, a11.y), fmaxf(a12.y, a13.y));
    float m1z = fmaxf(fmaxf(a10.z, a11.z), fmaxf(a12.z, a13.z));
    float m1w = fmaxf(fmaxf(a10.w, a11.w), fmaxf(a12.w, a13.w));

    float acc = fmaxf(m0x, m0y) + fmaxf(m0z, m0w)
              + fmaxf(m1x, m1y) + fmaxf(m1z, m1w);

    // Block reduction: warp shuffle, then smem across 8 warps.
    #pragma unroll
    for (int off = 16; off > 0; off >>= 1)
        acc += __shfl_xor_sync(0xFFFFFFFFu, acc, off);

    __shared__ float warp_sums[8];
    const int warp = tid >> 5;
    const int lane = tid & 31;
    if (lane == 0) warp_sums[warp] = acc;
    __syncthreads();

    if (warp == 0) {
        float v = (lane < 8) ? warp_sums[lane] : 0.0f;
        #pragma unroll
        for (int off = 4; off > 0; off >>= 1)
            v += __shfl_xor_sync(0xFFFFFFFFu, v, off);

        if (lane == 0) {
            atomicAdd(&g_scratch[n], v);
            __threadfence();
            // atomicInc wraps old==BLOCKS_PER_N-1 -> 0, so the counter is
            // automatically reset for the next launch/replay.
            unsigned int prev = atomicInc(&g_count[n], BLOCKS_PER_N - 1);
            if (prev == BLOCKS_PER_N - 1) {
                // Last block for this n: read+reset scratch, add bias sum.
                float total = atomicExch(&g_scratch[n], 0.0f);
                float bsum = 0.0f;
                #pragma unroll
                for (int cc = 0; cc < C_; ++cc)
                    bsum += __ldg(&bias[cc]);
                out[n] = total * SCALE_ + bsum;
            }
        }
    }
}

extern "C" void kernel_launch(void* const* d_in, const int* in_sizes, int n_in,
                              void* d_out, int out_size) {
    const float* o    = (const float*)d_in[0];
    const float* bias = (const float*)d_in[1];
    float* out = (float*)d_out;

    dim3 grid(PD_, C_, N_);   // 16 x 32 x 16 = 8192 blocks
    fused_pool_reduce_kernel<<<grid, 256>>>(o, bias, out);
}